// round 15
// baseline (speedup 1.0000x reference)
#include <cuda_runtime.h>

#define NQ 21
#define AD 18
#define NSTATE (1 << NQ)

typedef unsigned long long u64;

// 16MB statevector scratch, stored as packed complex: low 32 bits = re, high = im.
static __device__ u64   g_psi[NSTATE];
static __device__ float g_zd[NQ];   // sum |psi|^2 * (+1 if bit=0 else -1) per wire (FINAL state)
static __device__ float g_cr[NQ];   // Re sum psi(bit=0) conj(psi(bit=1)) (FINAL state)
static __device__ float g_ci[NQ];   // Im of same
static __device__ float g_S;

// ---------- packed f32x2 helpers ----------

__device__ __forceinline__ u64 pack2(float lo, float hi) {
    u64 d; asm("mov.b64 %0, {%1,%2};" : "=l"(d) : "f"(lo), "f"(hi)); return d;
}
__device__ __forceinline__ void unpack2(u64 d, float& lo, float& hi) {
    asm("mov.b64 {%0,%1}, %2;" : "=f"(lo), "=f"(hi) : "l"(d));
}
__device__ __forceinline__ float2 c2(u64 d) { float2 f; unpack2(d, f.x, f.y); return f; }
__device__ __forceinline__ u64 dswap(u64 d) {  // (re,im) -> (im,re)
    float lo, hi; unpack2(d, lo, hi); return pack2(hi, lo);
}
__device__ __forceinline__ u64 ffma2(u64 a, u64 b, u64 c) {
    u64 d; asm("fma.rn.f32x2 %0, %1, %2, %3;" : "=l"(d) : "l"(a), "l"(b), "l"(c)); return d;
}
__device__ __forceinline__ u64 fmul2(u64 a, u64 b) {
    u64 d; asm("mul.rn.f32x2 %0, %1, %2;" : "=l"(d) : "l"(a), "l"(b)); return d;
}
__device__ __forceinline__ float2 cmulc(float2 a, float2 b) {
    return make_float2(a.x * b.x - a.y * b.y, a.x * b.y + a.y * b.x);
}

// U = RZ(g)*RY(b)*RX(a); packed coeffs: for element E: (E.x,E.x), (-E.y,E.y).
__device__ void compute_U(const float* p, u64* C) {
    float sx, cx, sy, cy, sz, cz;
    sincosf(0.5f * p[0], &sx, &cx);
    sincosf(0.5f * p[1], &sy, &cy);
    sincosf(0.5f * p[2], &sz, &cz);
    float2 m00 = make_float2( cy * cx,  sy * sx);
    float2 m01 = make_float2(-sy * cx, -cy * sx);
    float2 m10 = make_float2( sy * cx, -cy * sx);
    float2 m11 = make_float2( cy * cx, -sy * sx);
    float2 ezm = make_float2(cz, -sz), ezp = make_float2(cz, sz);
    float2 U0 = cmulc(ezm, m00), U1 = cmulc(ezm, m01);
    float2 U2 = cmulc(ezp, m10), U3 = cmulc(ezp, m11);
    C[0] = pack2(U0.x, U0.x); C[1] = pack2(-U0.y, U0.y);
    C[2] = pack2(U1.x, U1.x); C[3] = pack2(-U1.y, U1.y);
    C[4] = pack2(U2.x, U2.x); C[5] = pack2(-U2.y, U2.y);
    C[6] = pack2(U3.x, U3.x); C[7] = pack2(-U3.y, U3.y);
}

// Gate on register bit J: pairs (r, r^(1<<J)) within the 16-amp register file.
template<int J>
__device__ __forceinline__ void reg_gate(u64* a, const u64* C) {
    u64 c0 = C[0], c1 = C[1], c2 = C[2], c3 = C[3];
    u64 c4 = C[4], c5 = C[5], c6 = C[6], c7 = C[7];
#pragma unroll
    for (int r = 0; r < 16; ++r) {
        if (!(r & (1 << J))) {
            u64 x0 = a[r], x1 = a[r ^ (1 << J)];
            u64 s0 = dswap(x0), s1 = dswap(x1);
            a[r]            = ffma2(c0, x0, ffma2(c1, s0, ffma2(c2, x1, fmul2(c3, s1))));
            a[r ^ (1 << J)] = ffma2(c4, x0, ffma2(c5, s0, ffma2(c6, x1, fmul2(c7, s1))));
        }
    }
}

// Gate on lane bit k via shfl_xor.
__device__ __forceinline__ void lane_gate(u64* a, int l, int k, const u64* C) {
    int bit = (l >> k) & 1;
    u64 d0 = bit ? C[6] : C[0];
    u64 d1 = bit ? C[7] : C[1];
    u64 d2 = bit ? C[4] : C[2];
    u64 d3 = bit ? C[5] : C[3];
#pragma unroll
    for (int r = 0; r < 16; ++r) {
        u64 p = __shfl_xor_sync(0xffffffffu, a[r], 1 << k);
        a[r] = ffma2(d0, a[r], ffma2(d1, dswap(a[r]), ffma2(d2, p, fmul2(d3, dswap(p)))));
    }
}

// ---------- reduction helpers ----------
__device__ __forceinline__ void wred(float v, float* dst) {
#pragma unroll
    for (int o = 16; o; o >>= 1) v += __shfl_down_sync(0xffffffffu, v, o);
    if ((threadIdx.x & 31) == 0) atomicAdd(dst, v);
}

// coherence over a lane-bit mask; sk = +-1 from this lane's selector bit(s)
__device__ __forceinline__ void lane_cm(const float2* A, int mask, float sk,
                                        float* red_re, float* red_im) {
    float cre = 0.f, cim = 0.f;
#pragma unroll
    for (int r = 0; r < 16; ++r) {
        float pr = __shfl_xor_sync(0xffffffffu, A[r].x, mask);
        float pi = __shfl_xor_sync(0xffffffffu, A[r].y, mask);
        float tre = fmaf(A[r].x, pr, A[r].y * pi);
        float tim = fmaf(A[r].y, pr, -A[r].x * pi);
        cre += tre;
        cim = fmaf(sk, tim, cim);
    }
    wred(0.5f * cre, red_re);
    wred(0.5f * cim, red_im);
}

// plain coherence on register bit J
template<int J>
__device__ __forceinline__ void reg_c(const float2* A, float* red_re, float* red_im) {
    float cre = 0.f, cim = 0.f;
#pragma unroll
    for (int r = 0; r < 16; ++r) {
        if (!(r & (1 << J))) {
            float2 x0 = A[r], x1 = A[r ^ (1 << J)];
            cre = fmaf(x0.x, x1.x, fmaf(x0.y, x1.y, cre));
            cim = fmaf(x0.y, x1.x, fmaf(-x0.x, x1.y, cim));
        }
    }
    wred(cre, red_re);
    wred(cim, red_im);
}

// ---------- pass H: local bits v0,v1 -> g0,g1 ; v2..v11 -> g11..g20 ----------
template<int FIRST, int DO_CNOT>
__global__ void __launch_bounds__(256, 4) pass_h(const float* __restrict__ params,
                                                 const float* __restrict__ state_in,
                                                 int layer) {
    __shared__ u64 s[4096];
    __shared__ u64 sC[NQ][8];
    int tid = threadIdx.x;
    int l = tid & 31, w = tid >> 5;
    int c = blockIdx.x;  // chunk = g2..g10

    if (FIRST && c == 0) {  // fold accumulator zeroing into layer-0 pass
        if (tid < NQ) { g_zd[tid] = 0.f; g_cr[tid] = 0.f; g_ci[tid] = 0.f; }
        if (tid == NQ) g_S = 0.f;
    }
    if (tid < NQ) compute_U(params + layer * 63 + tid * 3, sC[tid]);

    u64 a[16];
#pragma unroll
    for (int r = 0; r < 16; ++r) {
        int v = l | (r << 5) | (w << 9);
        int g = (v & 3) | (c << 2) | ((v >> 2) << 11);
        if (FIRST) a[r] = pack2(state_in[g], 0.0f);
        else       a[r] = g_psi[g];
    }
    __syncthreads();

    lane_gate(a, l, 2, sC[9]);
    lane_gate(a, l, 3, sC[8]);
    lane_gate(a, l, 4, sC[7]);
    reg_gate<0>(a, sC[6]);
    reg_gate<1>(a, sC[5]);
    reg_gate<2>(a, sC[4]);
    reg_gate<3>(a, sC[3]);

#pragma unroll
    for (int r = 0; r < 16; ++r) s[l | (r << 5) | (w << 9)] = a[r];
    __syncthreads();
#pragma unroll
    for (int r = 0; r < 16; ++r) a[r] = s[l | (w << 5) | (r << 8)];

    reg_gate<1>(a, sC[2]);
    reg_gate<2>(a, sC[1]);
    reg_gate<3>(a, sC[0]);

#pragma unroll
    for (int r = 0; r < 16; ++r) {
        int v = l | (w << 5) | (r << 8);
        int wv = v;
        if (DO_CNOT) {
            int x = v;
            x ^= x >> 1; x ^= x >> 2; x ^= x >> 4; x ^= x >> 8;
            wv = (v & ~0x7FC) | (x & 0x7FC);
        }
        int g = (wv & 3) | (c << 2) | ((wv >> 2) << 11);
        g_psi[g] = a[r];
    }
}

// ---------- pass L: local bits v0..v10 -> g0..g10 ; v11 -> g20 ----------
// MEAS=0: CNOT ring fold into store address (layers 0,1).
// MEAS=1 (layer 2): IDENTITY store; ring perm P_L applied VIRTUALLY via its
// GF(2) inverse, measurement of zd(all 21)+S+coherences(wires 0,10..20) fused
// here on the register state. m'_b = P_L^-1(e_b); selector y_b = sfx_b ^ cb.
template<int MEAS>
__global__ void __launch_bounds__(256, 4) pass_l(const float* __restrict__ params, int layer) {
    __shared__ u64 s[4096];
    __shared__ u64 sC[NQ][8];
    __shared__ float red[37];
    int tid = threadIdx.x;
    int l = tid & 31, w = tid >> 5;
    int c = blockIdx.x;  // chunk = g11..g19

    if (tid < NQ) compute_U(params + layer * 63 + tid * 3, sC[tid]);
    if (MEAS && tid < 37) red[tid] = 0.f;

    u64 a[16];
#pragma unroll
    for (int r = 0; r < 16; ++r) {
        int v = l | (r << 5) | (w << 9);
        int g = (v & 0x7FF) | (c << 11) | ((v >> 11) << 20);
        a[r] = g_psi[g];
    }
    __syncthreads();

    lane_gate(a, l, 0, sC[20]);
    lane_gate(a, l, 1, sC[19]);
    lane_gate(a, l, 2, sC[18]);
    lane_gate(a, l, 3, sC[17]);
    lane_gate(a, l, 4, sC[16]);
    reg_gate<0>(a, sC[15]);
    reg_gate<1>(a, sC[14]);
    reg_gate<2>(a, sC[13]);
    reg_gate<3>(a, sC[12]);

#pragma unroll
    for (int r = 0; r < 16; ++r) s[l | (r << 5) | (w << 9)] = a[r];
    __syncthreads();
#pragma unroll
    for (int r = 0; r < 16; ++r) a[r] = s[l | (w << 5) | (r << 8)];
    // phase-2 layout: lanes v0..v4 = l, warp v5..v7 = w, reg v8..v11 = r

    reg_gate<1>(a, sC[11]);
    reg_gate<2>(a, sC[10]);

    if (!MEAS) {
        int K = (c & 1) ? 0x7FF : 0;
#pragma unroll
        for (int r = 0; r < 16; ++r) {
            int v = l | (w << 5) | (r << 8);
            int u = v & 0x7FF;
            int x = u;
            x ^= x >> 1; x ^= x >> 2; x ^= x >> 4; x ^= x >> 8;
            int low = x ^ K;
            int wv = low | ((((v >> 11) ^ low) & 1) << 11);
            int g = (wv & 0x7FF) | (c << 11) | ((wv >> 11) << 20);
            g_psi[g] = a[r];
        }
    } else {
        // identity store (state pre-P_L; meas2 reads it the same way)
#pragma unroll
        for (int r = 0; r < 16; ++r) {
            int v = l | (w << 5) | (r << 8);
            int g = (v & 0x7FF) | (c << 11) | ((v >> 11) << 20);
            g_psi[g] = a[r];
        }

        // ---- fused measurement (virtual P_L) ----
        int tb = l | (w << 5);        // thread bits v0..v7
        int cb = c & 1;               // x'_11 (global bit 11)
        int A0 = __popc(tb) & 1;      // parity v0..v7

        // zd: y_b (b=0..10) = sfx_b(v0..v10)^cb ; y_20 = v11^y_0 ; y_11..19 = chunk
        float S = 0.f, tA = 0.f, t9 = 0.f, t10 = 0.f, t20 = 0.f;
#pragma unroll
        for (int r = 0; r < 16; ++r) {
            float2 x = c2(a[r]);
            float m = fmaf(x.x, x.x, x.y * x.y);
            S   += m;
            tA  += (__popc(r & 7) & 1)  ? -m : m;   // r0^r1^r2 (= v8^v9^v10)
            t9  += (__popc(r & 6) & 1)  ? -m : m;   // v9^v10
            t10 += (r & 4)              ? -m : m;   // v10
            t20 += (__popc(r & 15) & 1) ? -m : m;   // v8^v9^v10^v11
        }
        // slots: red[0]=wire0, red[1..11]=wires10..20, red[12]=S
#pragma unroll
        for (int b = 0; b < 8; ++b) {   // wires 20..13 (y bits 0..7)
            float v = ((__popc(tb >> b) & 1) ^ cb) ? -tA : tA;
            wred(v, &red[11 - b]);
        }
        wred(cb ? -tA : tA, &red[3]);                    // wire 12 (y8)
        wred(cb ? -t9 : t9, &red[2]);                    // wire 11 (y9)
        wred(cb ? -t10 : t10, &red[1]);                  // wire 10 (y10)
        wred((A0 ^ cb) ? -t20 : t20, &red[0]);           // wire 0  (y20)
        wred(S, &red[12]);

        // coherences: cre slots 13+k, cim slots 25+k (k = same slot map as zd)
        // W20 (slot 11): m' = v0^v11 -> shfl(a[r^8],1); sel = s012^A0^cb
        {
            float cre = 0.f, cim = 0.f;
#pragma unroll
            for (int r = 0; r < 16; ++r) {
                u64 pu = __shfl_xor_sync(0xffffffffu, a[r ^ 8], 1);
                float2 x = c2(a[r]), p = c2(pu);
                float tre = fmaf(x.x, p.x, x.y * p.y);
                float tim = fmaf(x.y, p.x, -x.x * p.y);
                cre += tre;
                int sel = (__popc(r & 7) & 1) ^ A0 ^ cb;
                cim += sel ? -tim : tim;
            }
            wred(0.5f * cre, &red[13 + 11]); wred(0.5f * cim, &red[25 + 11]);
        }
        // W19..W16 (slots 10..7): m' = v_{b-1}^v_b -> lane masks 3,6,12,24; sel = s012^A_b^cb
        {
            const int mk[4] = {3, 6, 12, 24};
#pragma unroll
            for (int b = 1; b <= 4; ++b) {
                int Ab = __popc(tb >> b) & 1;
                float cre = 0.f, cim = 0.f;
#pragma unroll
                for (int r = 0; r < 16; ++r) {
                    u64 pu = __shfl_xor_sync(0xffffffffu, a[r], mk[b - 1]);
                    float2 x = c2(a[r]), p = c2(pu);
                    float tre = fmaf(x.x, p.x, x.y * p.y);
                    float tim = fmaf(x.y, p.x, -x.x * p.y);
                    cre += tre;
                    int sel = (__popc(r & 7) & 1) ^ Ab ^ cb;
                    cim += sel ? -tim : tim;
                }
                wred(0.5f * cre, &red[13 + 11 - b]); wred(0.5f * cim, &red[25 + 11 - b]);
            }
        }
        // W11 (slot 2): m' = v8^v9 -> r^3 ; sel = (v9^v10)^cb
        {
            float cre = 0.f, cim = 0.f;
#pragma unroll
            for (int r = 0; r < 16; ++r) {
                float2 x = c2(a[r]), p = c2(a[r ^ 3]);
                float tre = fmaf(x.x, p.x, x.y * p.y);
                float tim = fmaf(x.y, p.x, -x.x * p.y);
                cre += tre;
                int sel = (__popc(r & 6) & 1) ^ cb;
                cim += sel ? -tim : tim;
            }
            wred(0.5f * cre, &red[13 + 2]); wred(0.5f * cim, &red[25 + 2]);
        }
        // W10 (slot 1): m' = v9^v10 -> r^6 ; sel = v10^cb
        {
            float cre = 0.f, cim = 0.f;
#pragma unroll
            for (int r = 0; r < 16; ++r) {
                float2 x = c2(a[r]), p = c2(a[r ^ 6]);
                float tre = fmaf(x.x, p.x, x.y * p.y);
                float tim = fmaf(x.y, p.x, -x.x * p.y);
                cre += tre;
                int sel = ((r >> 2) & 1) ^ cb;
                cim += sel ? -tim : tim;
            }
            wred(0.5f * cre, &red[13 + 1]); wred(0.5f * cim, &red[25 + 1]);
        }
        // W0 (slot 0): m' = v11 -> r^8 ; sel = v11^sfx0^cb = popc(r&15)^A0^cb
        {
            float cre = 0.f, cim = 0.f;
#pragma unroll
            for (int r = 0; r < 16; ++r) {
                float2 x = c2(a[r]), p = c2(a[r ^ 8]);
                float tre = fmaf(x.x, p.x, x.y * p.y);
                float tim = fmaf(x.y, p.x, -x.x * p.y);
                cre += tre;
                int sel = (__popc(r & 15) & 1) ^ A0 ^ cb;
                cim += sel ? -tim : tim;
            }
            wred(0.5f * cre, &red[13 + 0]); wred(0.5f * cim, &red[25 + 0]);
        }

        // exchange back to phase-1 layout (lanes v0..v4, reg v5..v8, warp v9..v11)
        __syncthreads();
#pragma unroll
        for (int r = 0; r < 16; ++r) s[l | (w << 5) | (r << 8)] = a[r];
        __syncthreads();
#pragma unroll
        for (int r = 0; r < 16; ++r) a[r] = s[l | (r << 5) | (w << 9)];

        int pw2 = __popc(w & 3) & 1;   // v9^v10
        // W15 (slot 6): m' = v4^v5 -> shfl(a[r^1],16); sel = popc(r)^pw2^cb
        {
            float cre = 0.f, cim = 0.f;
#pragma unroll
            for (int r = 0; r < 16; ++r) {
                u64 pu = __shfl_xor_sync(0xffffffffu, a[r ^ 1], 16);
                float2 x = c2(a[r]), p = c2(pu);
                float tre = fmaf(x.x, p.x, x.y * p.y);
                float tim = fmaf(x.y, p.x, -x.x * p.y);
                cre += tre;
                int sel = (__popc(r) & 1) ^ pw2 ^ cb;
                cim += sel ? -tim : tim;
            }
            wred(0.5f * cre, &red[13 + 6]); wred(0.5f * cim, &red[25 + 6]);
        }
        // W14 (slot 5): m' = v5^v6 -> r^3 ; sel = popc(r&0xE)^pw2^cb
        {
            float cre = 0.f, cim = 0.f;
#pragma unroll
            for (int r = 0; r < 16; ++r) {
                float2 x = c2(a[r]), p = c2(a[r ^ 3]);
                float tre = fmaf(x.x, p.x, x.y * p.y);
                float tim = fmaf(x.y, p.x, -x.x * p.y);
                cre += tre;
                int sel = (__popc(r & 0xE) & 1) ^ pw2 ^ cb;
                cim += sel ? -tim : tim;
            }
            wred(0.5f * cre, &red[13 + 5]); wred(0.5f * cim, &red[25 + 5]);
        }
        // W13 (slot 4): m' = v6^v7 -> r^6 ; sel = popc(r&0xC)^pw2^cb
        {
            float cre = 0.f, cim = 0.f;
#pragma unroll
            for (int r = 0; r < 16; ++r) {
                float2 x = c2(a[r]), p = c2(a[r ^ 6]);
                float tre = fmaf(x.x, p.x, x.y * p.y);
                float tim = fmaf(x.y, p.x, -x.x * p.y);
                cre += tre;
                int sel = (__popc(r & 0xC) & 1) ^ pw2 ^ cb;
                cim += sel ? -tim : tim;
            }
            wred(0.5f * cre, &red[13 + 4]); wred(0.5f * cim, &red[25 + 4]);
        }
        // W12 (slot 3): m' = v7^v8 -> r^12 ; sel = v8^pw2^cb = (r>>3)^pw2^cb
        {
            float cre = 0.f, cim = 0.f;
#pragma unroll
            for (int r = 0; r < 16; ++r) {
                float2 x = c2(a[r]), p = c2(a[r ^ 12]);
                float tre = fmaf(x.x, p.x, x.y * p.y);
                float tim = fmaf(x.y, p.x, -x.x * p.y);
                cre += tre;
                int sel = ((r >> 3) & 1) ^ pw2 ^ cb;
                cim += sel ? -tim : tim;
            }
            wred(0.5f * cre, &red[13 + 3]); wred(0.5f * cim, &red[25 + 3]);
        }

        __syncthreads();
        if (tid < 12) {
            int q = (tid == 0) ? 0 : 9 + tid;   // slots -> wires {0,10..20}
            atomicAdd(&g_zd[q], red[tid]);
            atomicAdd(&g_cr[q], red[13 + tid]);
            atomicAdd(&g_ci[q], red[25 + tid]);
        } else if (tid == 12) {
            atomicAdd(&g_S, red[12]);
        } else if (tid == 13) {
            float Sb = red[12];
#pragma unroll
            for (int q = 1; q <= 9; ++q)   // y bit 20-q = chunk bit 9-q
                atomicAdd(&g_zd[q], ((c >> (9 - q)) & 1) ? -Sb : Sb);
        }
    }
}

// ---------- meas2: coherences for wires 1..9 on the identity-stored state ----
// Tiling: v0,v1->g0,g1 ; v2..v11->g10..g19. Chunk: c0..c7->g2..g9, c8->g20.
// Stored-domain masks: wire9: m'=g10^g11 (v2^v3), sel=g11(v3); wires 8..1:
// plain bits g12..g19 (v4..v11).
__global__ void __launch_bounds__(256, 4) meas2() {
    __shared__ float2 s[4096];
    __shared__ float red[18];   // [0..8]=cre wires1..9, [9..17]=cim
    int tid = threadIdx.x;
    int l = tid & 31, w = tid >> 5;
    int c = blockIdx.x;
    const float2* ps = (const float2*)g_psi;

    if (tid < 18) red[tid] = 0.f;
    __syncthreads();

    float2 A[16];
#pragma unroll
    for (int r = 0; r < 16; ++r) {
        int v = l | (r << 5) | (w << 9);
        int g = (v & 3) | ((c & 0xFF) << 2) | (((v >> 2) & 0x3FF) << 10) | ((c >> 8) << 20);
        A[r] = ps[g];
    }

    float s3 = (l & 8)  ? -1.f : 1.f;
    float s4 = (l & 16) ? -1.f : 1.f;
    lane_cm(A, 0xC, s3, &red[8], &red[17]);   // wire9 : pair v2^v3, sel=v3
    lane_cm(A, 0x10, s4, &red[7], &red[16]);  // wire8 : v4
    reg_c<0>(A, &red[6], &red[15]);           // wire7 : v5
    reg_c<1>(A, &red[5], &red[14]);           // wire6 : v6
    reg_c<2>(A, &red[4], &red[13]);           // wire5 : v7
    reg_c<3>(A, &red[3], &red[12]);           // wire4 : v8

#pragma unroll
    for (int r = 0; r < 16; ++r) s[l | (r << 5) | (w << 9)] = A[r];
    __syncthreads();
#pragma unroll
    for (int r = 0; r < 16; ++r) A[r] = s[l | (w << 5) | (r << 8)];
    // reg now covers v8..v11

    reg_c<1>(A, &red[2], &red[11]);           // wire3 : v9
    reg_c<2>(A, &red[1], &red[10]);           // wire2 : v10
    reg_c<3>(A, &red[0], &red[9]);            // wire1 : v11

    __syncthreads();
    if (tid < 9) {
        atomicAdd(&g_cr[1 + tid], red[tid]);
        atomicAdd(&g_ci[1 + tid], red[9 + tid]);
    }
}

// ---------- head ----------
__global__ void head_kernel(const float* __restrict__ params,
                            const float* __restrict__ w, const float* __restrict__ b,
                            float* __restrict__ out) {
    __shared__ float smeas[NQ];
    __shared__ float slog[AD];
    int t = threadIdx.x;
    float S = g_S;
    float inv = (S > 0.0f) ? (1.0f / S) : 0.0f;
    if (t < NQ) {
        const float* p = params + 3 * 63 + t * 3;
        float sx, cx, sy, cy, sz, cz;
        sincosf(0.5f * p[0], &sx, &cx);
        sincosf(0.5f * p[1], &sy, &cy);
        sincosf(0.5f * p[2], &sz, &cz);
        float2 m00 = make_float2( cy * cx,  sy * sx);
        float2 m01 = make_float2(-sy * cx, -cy * sx);
        float2 m10 = make_float2( sy * cx, -cy * sx);
        float2 m11 = make_float2( cy * cx, -sy * sx);
        float2 ezm = make_float2(cz, -sz), ezp = make_float2(cz, sz);
        float2 a = cmulc(ezm, m00);   // u00
        float2 bb = cmulc(ezm, m01);  // u01
        float2 cc = cmulc(ezp, m10);  // u10
        float2 d = cmulc(ezp, m11);   // u11
        float M00 = (a.x * a.x + a.y * a.y) - (cc.x * cc.x + cc.y * cc.y);
        float M10r = (bb.x * a.x + bb.y * a.y) - (d.x * cc.x + d.y * cc.y);
        float M10i = (bb.x * a.y - bb.y * a.x) - (d.x * cc.y - d.y * cc.x);
        smeas[t] = (M00 * g_zd[t] + 2.0f * (M10r * g_cr[t] - M10i * g_ci[t])) * inv;
    }
    __syncthreads();
    if (t < AD) {
        float acc = b[t];
#pragma unroll
        for (int q = 0; q < NQ; ++q) acc = fmaf(w[t * NQ + q], smeas[q], acc);
        slog[t] = acc;
    }
    __syncthreads();
    if (t == 0) {
        float mx = -1e30f;
        for (int ai = 0; ai < AD; ++ai) if (slog[ai] > mx) mx = slog[ai];
        float sum = 0.0f;
        float e[AD];
        for (int ai = 0; ai < AD; ++ai) { e[ai] = expf(slog[ai] - mx); sum += e[ai]; }
        float is = 1.0f / sum;
        for (int ai = 0; ai < AD; ++ai) out[ai] = e[ai] * is;
    }
}

// ---------- launch ----------
extern "C" void kernel_launch(void* const* d_in, const int* in_sizes, int n_in,
                              void* d_out, int out_size) {
    const float* state  = (const float*)d_in[0];  // 2^21 float32
    const float* params = (const float*)d_in[1];  // 252 float32
    const float* hw     = (const float*)d_in[2];  // 18*21 float32
    const float* hb     = (const float*)d_in[3];  // 18 float32
    float* out = (float*)d_out;

    pass_h<1, 1><<<512, 256>>>(params, state, 0);
    pass_l<0><<<512, 256>>>(params, 0);
    pass_h<0, 1><<<512, 256>>>(params, state, 1);
    pass_l<0><<<512, 256>>>(params, 1);
    pass_h<0, 1><<<512, 256>>>(params, state, 2);
    pass_l<1><<<512, 256>>>(params, 2);
    meas2<<<512, 256>>>();
    head_kernel<<<1, 32>>>(params, hw, hb, out);
}

// round 16
// speedup vs baseline: 1.1217x; 1.1217x over previous
#include <cuda_runtime.h>

#define NQ 21
#define AD 18
#define NSTATE (1 << NQ)

typedef unsigned long long u64;

// 16MB statevector scratch, stored as packed complex: low 32 bits = re, high = im.
static __device__ u64   g_psi[NSTATE];
static __device__ float g_zd[NQ];   // sum |psi|^2 * (+1 if bit=0 else -1) per wire
static __device__ float g_cr[NQ];   // Re sum psi(bit=0) conj(psi(bit=1))
static __device__ float g_ci[NQ];   // Im of same
static __device__ float g_S;

// ---------- packed f32x2 helpers ----------

__device__ __forceinline__ u64 pack2(float lo, float hi) {
    u64 d; asm("mov.b64 %0, {%1,%2};" : "=l"(d) : "f"(lo), "f"(hi)); return d;
}
__device__ __forceinline__ void unpack2(u64 d, float& lo, float& hi) {
    asm("mov.b64 {%0,%1}, %2;" : "=f"(lo), "=f"(hi) : "l"(d));
}
__device__ __forceinline__ u64 dswap(u64 d) {  // (re,im) -> (im,re)
    float lo, hi; unpack2(d, lo, hi); return pack2(hi, lo);
}
__device__ __forceinline__ u64 ffma2(u64 a, u64 b, u64 c) {
    u64 d; asm("fma.rn.f32x2 %0, %1, %2, %3;" : "=l"(d) : "l"(a), "l"(b), "l"(c)); return d;
}
__device__ __forceinline__ u64 fmul2(u64 a, u64 b) {
    u64 d; asm("mul.rn.f32x2 %0, %1, %2;" : "=l"(d) : "l"(a), "l"(b)); return d;
}

__device__ __forceinline__ float2 cmulc(float2 a, float2 b) {
    return make_float2(a.x * b.x - a.y * b.y, a.x * b.y + a.y * b.x);
}

// U = RZ(g)*RY(b)*RX(a); packed coeffs: for element E: (E.x,E.x), (-E.y,E.y).
__device__ void compute_U(const float* p, u64* C) {
    float sx, cx, sy, cy, sz, cz;
    sincosf(0.5f * p[0], &sx, &cx);
    sincosf(0.5f * p[1], &sy, &cy);
    sincosf(0.5f * p[2], &sz, &cz);
    float2 m00 = make_float2( cy * cx,  sy * sx);
    float2 m01 = make_float2(-sy * cx, -cy * sx);
    float2 m10 = make_float2( sy * cx, -cy * sx);
    float2 m11 = make_float2( cy * cx, -sy * sx);
    float2 ezm = make_float2(cz, -sz), ezp = make_float2(cz, sz);
    float2 U0 = cmulc(ezm, m00), U1 = cmulc(ezm, m01);
    float2 U2 = cmulc(ezp, m10), U3 = cmulc(ezp, m11);
    C[0] = pack2(U0.x, U0.x); C[1] = pack2(-U0.y, U0.y);
    C[2] = pack2(U1.x, U1.x); C[3] = pack2(-U1.y, U1.y);
    C[4] = pack2(U2.x, U2.x); C[5] = pack2(-U2.y, U2.y);
    C[6] = pack2(U3.x, U3.x); C[7] = pack2(-U3.y, U3.y);
}

// Gate on register bit J: pairs (r, r^(1<<J)) within the 16-amp register file.
template<int J>
__device__ __forceinline__ void reg_gate(u64* a, const u64* C) {
    u64 c0 = C[0], c1 = C[1], c2 = C[2], c3 = C[3];
    u64 c4 = C[4], c5 = C[5], c6 = C[6], c7 = C[7];
#pragma unroll
    for (int r = 0; r < 16; ++r) {
        if (!(r & (1 << J))) {
            u64 x0 = a[r], x1 = a[r ^ (1 << J)];
            u64 s0 = dswap(x0), s1 = dswap(x1);
            a[r]            = ffma2(c0, x0, ffma2(c1, s0, ffma2(c2, x1, fmul2(c3, s1))));
            a[r ^ (1 << J)] = ffma2(c4, x0, ffma2(c5, s0, ffma2(c6, x1, fmul2(c7, s1))));
        }
    }
}

// Gate on lane bit k via shfl_xor.
__device__ __forceinline__ void lane_gate(u64* a, int l, int k, const u64* C) {
    int bit = (l >> k) & 1;
    u64 d0 = bit ? C[6] : C[0];
    u64 d1 = bit ? C[7] : C[1];
    u64 d2 = bit ? C[4] : C[2];
    u64 d3 = bit ? C[5] : C[3];
#pragma unroll
    for (int r = 0; r < 16; ++r) {
        u64 p = __shfl_xor_sync(0xffffffffu, a[r], 1 << k);
        a[r] = ffma2(d0, a[r], ffma2(d1, dswap(a[r]), ffma2(d2, p, fmul2(d3, dswap(p)))));
    }
}

// ---------- pass H: local bits v0,v1 -> g0,g1 ; v2..v11 -> g11..g20 ----------
template<int FIRST, int DO_CNOT>
__global__ void __launch_bounds__(256, 4) pass_h(const float* __restrict__ params,
                                                 const float* __restrict__ state_in,
                                                 int layer) {
    __shared__ u64 s[4096];
    __shared__ u64 sC[NQ][8];
    int tid = threadIdx.x;
    int l = tid & 31, w = tid >> 5;
    int c = blockIdx.x;  // chunk = g2..g10

    // loads first: start the ~600-cycle global latency before any MUFU work
    u64 a[16];
#pragma unroll
    for (int r = 0; r < 16; ++r) {
        int v = l | (r << 5) | (w << 9);
        int g = (v & 3) | (c << 2) | ((v >> 2) << 11);
        if (FIRST) a[r] = pack2(state_in[g], 0.0f);
        else       a[r] = g_psi[g];
    }

    if (FIRST && c == 0) {  // fold accumulator zeroing into layer-0 pass
        if (tid < NQ) { g_zd[tid] = 0.f; g_cr[tid] = 0.f; g_ci[tid] = 0.f; }
        if (tid == NQ) g_S = 0.f;
    }
    if (tid < NQ) compute_U(params + layer * 63 + tid * 3, sC[tid]);
    __syncthreads();

    lane_gate(a, l, 2, sC[9]);
    lane_gate(a, l, 3, sC[8]);
    lane_gate(a, l, 4, sC[7]);
    reg_gate<0>(a, sC[6]);
    reg_gate<1>(a, sC[5]);
    reg_gate<2>(a, sC[4]);
    reg_gate<3>(a, sC[3]);

#pragma unroll
    for (int r = 0; r < 16; ++r) s[l | (r << 5) | (w << 9)] = a[r];
    __syncthreads();
#pragma unroll
    for (int r = 0; r < 16; ++r) a[r] = s[l | (w << 5) | (r << 8)];

    reg_gate<1>(a, sC[2]);
    reg_gate<2>(a, sC[1]);
    reg_gate<3>(a, sC[0]);

#pragma unroll
    for (int r = 0; r < 16; ++r) {
        int v = l | (w << 5) | (r << 8);
        int wv = v;
        if (DO_CNOT) {
            int x = v;
            x ^= x >> 1; x ^= x >> 2; x ^= x >> 4; x ^= x >> 8;
            wv = (v & ~0x7FC) | (x & 0x7FC);
        }
        int g = (wv & 3) | (c << 2) | ((wv >> 2) << 11);
        g_psi[g] = a[r];
    }
}

// ---------- pass L: local bits v0..v10 -> g0..g10 ; v11 -> g20 ----------
__global__ void __launch_bounds__(256, 4) pass_l(const float* __restrict__ params, int layer) {
    __shared__ u64 s[4096];
    __shared__ u64 sC[NQ][8];
    int tid = threadIdx.x;
    int l = tid & 31, w = tid >> 5;
    int c = blockIdx.x;  // chunk = g11..g19

    u64 a[16];
#pragma unroll
    for (int r = 0; r < 16; ++r) {
        int v = l | (r << 5) | (w << 9);
        int g = (v & 0x7FF) | (c << 11) | ((v >> 11) << 20);
        a[r] = g_psi[g];
    }

    if (tid < NQ) compute_U(params + layer * 63 + tid * 3, sC[tid]);
    __syncthreads();

    lane_gate(a, l, 0, sC[20]);
    lane_gate(a, l, 1, sC[19]);
    lane_gate(a, l, 2, sC[18]);
    lane_gate(a, l, 3, sC[17]);
    lane_gate(a, l, 4, sC[16]);
    reg_gate<0>(a, sC[15]);
    reg_gate<1>(a, sC[14]);
    reg_gate<2>(a, sC[13]);
    reg_gate<3>(a, sC[12]);

#pragma unroll
    for (int r = 0; r < 16; ++r) s[l | (r << 5) | (w << 9)] = a[r];
    __syncthreads();
#pragma unroll
    for (int r = 0; r < 16; ++r) a[r] = s[l | (w << 5) | (r << 8)];

    reg_gate<1>(a, sC[11]);
    reg_gate<2>(a, sC[10]);

    int K = (c & 1) ? 0x7FF : 0;
#pragma unroll
    for (int r = 0; r < 16; ++r) {
        int v = l | (w << 5) | (r << 8);
        int u = v & 0x7FF;
        int x = u;
        x ^= x >> 1; x ^= x >> 2; x ^= x >> 4; x ^= x >> 8;
        int low = x ^ K;
        int wv = low | ((((v >> 11) ^ low) & 1) << 11);
        int g = (wv & 0x7FF) | (c << 11) | ((wv >> 11) << 20);
        g_psi[g] = a[r];
    }
}

// ---------- measurement reductions ----------
// After layer 2 (state in g_psi), layer 3 = 21 commuting 1-qubit rotations then
// Z measurement. Z'_q = M00*(d0-d1) + 2 Re(c_q * M10) with M = U_q^dag Z U_q,
// c_q = sum psi(bit=0) conj(psi(bit=1)). Only (zd, c) reductions needed here.

__device__ __forceinline__ void wred(float v, float* dst) {
#pragma unroll
    for (int o = 16; o; o >>= 1) v += __shfl_down_sync(0xffffffffu, v, o);
    if ((threadIdx.x & 31) == 0) atomicAdd(dst, v);
}

__device__ __forceinline__ void lane_c(const float2* A, int l, int k, float sk,
                                       float* red_re, float* red_im) {
    float cre = 0.f, cim = 0.f;
#pragma unroll
    for (int r = 0; r < 16; ++r) {
        float pr = __shfl_xor_sync(0xffffffffu, A[r].x, 1 << k);
        float pi = __shfl_xor_sync(0xffffffffu, A[r].y, 1 << k);
        float tre = fmaf(A[r].x, pr, A[r].y * pi);
        float tim = fmaf(A[r].y, pr, -A[r].x * pi);
        cre += tre;
        cim = fmaf(sk, tim, cim);
    }
    wred(0.5f * cre, red_re);
    wred(0.5f * cim, red_im);
}

template<int J>
__device__ __forceinline__ void reg_c(const float2* A, float* red_re, float* red_im) {
    float cre = 0.f, cim = 0.f;
#pragma unroll
    for (int r = 0; r < 16; ++r) {
        if (!(r & (1 << J))) {
            float2 x0 = A[r], x1 = A[r ^ (1 << J)];
            cre = fmaf(x0.x, x1.x, fmaf(x0.y, x1.y, cre));
            cim = fmaf(x0.y, x1.x, fmaf(-x0.x, x1.y, cim));
        }
    }
    wred(cre, red_re);
    wred(cim, red_im);
}

// meas_hl: merged H-tiling (blocks 0..511) + L-tiling (512..1023).
// occ 5 -> 740 CTA slots -> 1.38 waves instead of 1.73.
__global__ void __launch_bounds__(256, 5) meas_hl() {
    __shared__ float2 s[4096];
    __shared__ float red[33];
    int tid = threadIdx.x;
    int l = tid & 31, w = tid >> 5;
    const float2* ps = (const float2*)g_psi;

    if (tid < 33) red[tid] = 0.f;
    __syncthreads();

    if (blockIdx.x < 512) {
        // H tiling: wires 0..9 (bits g11..g20) + S
        int c = blockIdx.x;
        float2 A[16];
#pragma unroll
        for (int r = 0; r < 16; ++r) {
            int v = l | (r << 5) | (w << 9);
            int g = (v & 3) | (c << 2) | ((v >> 2) << 11);
            A[r] = ps[g];
        }

        float S = 0.f, z5 = 0.f, z6 = 0.f, z7 = 0.f, z8 = 0.f;
#pragma unroll
        for (int r = 0; r < 16; ++r) {
            float m = fmaf(A[r].x, A[r].x, A[r].y * A[r].y);
            S += m;
            z5 += (r & 1) ? -m : m;
            z6 += (r & 2) ? -m : m;
            z7 += (r & 4) ? -m : m;
            z8 += (r & 8) ? -m : m;
        }
        float s2 = (l & 4)  ? -1.f : 1.f;
        float s3 = (l & 8)  ? -1.f : 1.f;
        float s4 = (l & 16) ? -1.f : 1.f;
        wred(s2 * S, &red[9]);   // v2 -> wire 9
        wred(s3 * S, &red[8]);
        wred(s4 * S, &red[7]);
        wred(z5, &red[6]);
        wred(z6, &red[5]);
        wred(z7, &red[4]);
        wred(z8, &red[3]);
        wred(((w & 1) ? -S : S), &red[2]);  // v9 -> wire 2
        wred(((w & 2) ? -S : S), &red[1]);
        wred(((w & 4) ? -S : S), &red[0]);
        wred(S, &red[10]);

        lane_c(A, l, 2, s2, &red[11 + 9], &red[21 + 9]);
        lane_c(A, l, 3, s3, &red[11 + 8], &red[21 + 8]);
        lane_c(A, l, 4, s4, &red[11 + 7], &red[21 + 7]);
        reg_c<0>(A, &red[11 + 6], &red[21 + 6]);
        reg_c<1>(A, &red[11 + 5], &red[21 + 5]);
        reg_c<2>(A, &red[11 + 4], &red[21 + 4]);

#pragma unroll
        for (int r = 0; r < 16; ++r) s[l | (r << 5) | (w << 9)] = A[r];
        __syncthreads();
#pragma unroll
        for (int r = 0; r < 16; ++r) A[r] = s[l | (w << 5) | (r << 8)];

        reg_c<0>(A, &red[11 + 3], &red[21 + 3]);
        reg_c<1>(A, &red[11 + 2], &red[21 + 2]);
        reg_c<2>(A, &red[11 + 1], &red[21 + 1]);
        reg_c<3>(A, &red[11 + 0], &red[21 + 0]);

        __syncthreads();
        if (tid < 10) {
            atomicAdd(&g_zd[tid], red[tid]);
            atomicAdd(&g_cr[tid], red[11 + tid]);
            atomicAdd(&g_ci[tid], red[21 + tid]);
        }
        if (tid == 10) atomicAdd(&g_S, red[10]);
    } else {
        // L tiling: wires 10..20 (bits g0..g10)
        int c = blockIdx.x - 512;
        float2 A[16];
#pragma unroll
        for (int r = 0; r < 16; ++r) {
            int v = l | (r << 5) | (w << 9);
            int g = (v & 0x7FF) | (c << 11) | ((v >> 11) << 20);
            A[r] = ps[g];
        }

        float S = 0.f, z5 = 0.f, z6 = 0.f, z7 = 0.f, z8 = 0.f;
#pragma unroll
        for (int r = 0; r < 16; ++r) {
            float m = fmaf(A[r].x, A[r].x, A[r].y * A[r].y);
            S += m;
            z5 += (r & 1) ? -m : m;
            z6 += (r & 2) ? -m : m;
            z7 += (r & 4) ? -m : m;
            z8 += (r & 8) ? -m : m;
        }
        float s0 = (l & 1)  ? -1.f : 1.f;
        float s1 = (l & 2)  ? -1.f : 1.f;
        float s2 = (l & 4)  ? -1.f : 1.f;
        float s3 = (l & 8)  ? -1.f : 1.f;
        float s4 = (l & 16) ? -1.f : 1.f;
        wred(s0 * S, &red[10]);   // wire 20
        wred(s1 * S, &red[9]);
        wred(s2 * S, &red[8]);
        wred(s3 * S, &red[7]);
        wred(s4 * S, &red[6]);
        wred(z5, &red[5]);
        wred(z6, &red[4]);
        wred(z7, &red[3]);
        wred(z8, &red[2]);
        wred(((w & 1) ? -S : S), &red[1]);   // wire 11
        wred(((w & 2) ? -S : S), &red[0]);   // wire 10

        lane_c(A, l, 0, s0, &red[11 + 10], &red[22 + 10]);
        lane_c(A, l, 1, s1, &red[11 + 9],  &red[22 + 9]);
        lane_c(A, l, 2, s2, &red[11 + 8],  &red[22 + 8]);
        lane_c(A, l, 3, s3, &red[11 + 7],  &red[22 + 7]);
        lane_c(A, l, 4, s4, &red[11 + 6],  &red[22 + 6]);
        reg_c<0>(A, &red[11 + 5], &red[22 + 5]);
        reg_c<1>(A, &red[11 + 4], &red[22 + 4]);
        reg_c<2>(A, &red[11 + 3], &red[22 + 3]);

#pragma unroll
        for (int r = 0; r < 16; ++r) s[l | (r << 5) | (w << 9)] = A[r];
        __syncthreads();
#pragma unroll
        for (int r = 0; r < 16; ++r) A[r] = s[l | (w << 5) | (r << 8)];

        reg_c<0>(A, &red[11 + 2], &red[22 + 2]);
        reg_c<1>(A, &red[11 + 1], &red[22 + 1]);
        reg_c<2>(A, &red[11 + 0], &red[22 + 0]);

        __syncthreads();
        if (tid < 11) {
            atomicAdd(&g_zd[10 + tid], red[tid]);
            atomicAdd(&g_cr[10 + tid], red[11 + tid]);
            atomicAdd(&g_ci[10 + tid], red[22 + tid]);
        }
    }
}

// ---------- head ----------
__global__ void head_kernel(const float* __restrict__ params,
                            const float* __restrict__ w, const float* __restrict__ b,
                            float* __restrict__ out) {
    __shared__ float smeas[NQ];
    __shared__ float slog[AD];
    int t = threadIdx.x;
    float S = g_S;
    float inv = (S > 0.0f) ? (1.0f / S) : 0.0f;
    if (t < NQ) {
        const float* p = params + 3 * 63 + t * 3;
        float sx, cx, sy, cy, sz, cz;
        sincosf(0.5f * p[0], &sx, &cx);
        sincosf(0.5f * p[1], &sy, &cy);
        sincosf(0.5f * p[2], &sz, &cz);
        float2 m00 = make_float2( cy * cx,  sy * sx);
        float2 m01 = make_float2(-sy * cx, -cy * sx);
        float2 m10 = make_float2( sy * cx, -cy * sx);
        float2 m11 = make_float2( cy * cx, -sy * sx);
        float2 ezm = make_float2(cz, -sz), ezp = make_float2(cz, sz);
        float2 a = cmulc(ezm, m00);   // u00
        float2 bb = cmulc(ezm, m01);  // u01
        float2 cc = cmulc(ezp, m10);  // u10
        float2 d = cmulc(ezp, m11);   // u11
        float M00 = (a.x * a.x + a.y * a.y) - (cc.x * cc.x + cc.y * cc.y);
        float M10r = (bb.x * a.x + bb.y * a.y) - (d.x * cc.x + d.y * cc.y);
        float M10i = (bb.x * a.y - bb.y * a.x) - (d.x * cc.y - d.y * cc.x);
        smeas[t] = (M00 * g_zd[t] + 2.0f * (M10r * g_cr[t] - M10i * g_ci[t])) * inv;
    }
    __syncthreads();
    if (t < AD) {
        float acc = b[t];
#pragma unroll
        for (int q = 0; q < NQ; ++q) acc = fmaf(w[t * NQ + q], smeas[q], acc);
        slog[t] = acc;
    }
    __syncthreads();
    if (t == 0) {
        float mx = -1e30f;
        for (int ai = 0; ai < AD; ++ai) if (slog[ai] > mx) mx = slog[ai];
        float sum = 0.0f;
        float e[AD];
        for (int ai = 0; ai < AD; ++ai) { e[ai] = expf(slog[ai] - mx); sum += e[ai]; }
        float is = 1.0f / sum;
        for (int ai = 0; ai < AD; ++ai) out[ai] = e[ai] * is;
    }
}

// ---------- launch ----------
extern "C" void kernel_launch(void* const* d_in, const int* in_sizes, int n_in,
                              void* d_out, int out_size) {
    const float* state  = (const float*)d_in[0];  // 2^21 float32
    const float* params = (const float*)d_in[1];  // 252 float32
    const float* hw     = (const float*)d_in[2];  // 18*21 float32
    const float* hb     = (const float*)d_in[3];  // 18 float32
    float* out = (float*)d_out;

    pass_h<1, 1><<<512, 256>>>(params, state, 0);
    pass_l<<<512, 256>>>(params, 0);
    pass_h<0, 1><<<512, 256>>>(params, state, 1);
    pass_l<<<512, 256>>>(params, 1);
    pass_h<0, 1><<<512, 256>>>(params, state, 2);
    pass_l<<<512, 256>>>(params, 2);
    meas_hl<<<1024, 256>>>();
    head_kernel<<<1, 32>>>(params, hw, hb, out);
}

// round 17
// speedup vs baseline: 1.2000x; 1.0698x over previous
#include <cuda_runtime.h>

#define NQ 21
#define AD 18
#define NSTATE (1 << NQ)

typedef unsigned long long u64;

// 16MB statevector scratch, stored as packed complex: low 32 bits = re, high = im.
static __device__ u64   g_psi[NSTATE];
static __device__ float g_zd[NQ];   // sum |psi|^2 * (+1 if bit=0 else -1) per wire
static __device__ float g_cr[NQ];   // Re sum psi(bit=0) conj(psi(bit=1))
static __device__ float g_ci[NQ];   // Im of same
static __device__ float g_S;

// ---------- packed f32x2 helpers ----------

__device__ __forceinline__ u64 pack2(float lo, float hi) {
    u64 d; asm("mov.b64 %0, {%1,%2};" : "=l"(d) : "f"(lo), "f"(hi)); return d;
}
__device__ __forceinline__ void unpack2(u64 d, float& lo, float& hi) {
    asm("mov.b64 {%0,%1}, %2;" : "=f"(lo), "=f"(hi) : "l"(d));
}
__device__ __forceinline__ u64 dswap(u64 d) {  // (re,im) -> (im,re)
    float lo, hi; unpack2(d, lo, hi); return pack2(hi, lo);
}
__device__ __forceinline__ u64 ffma2(u64 a, u64 b, u64 c) {
    u64 d; asm("fma.rn.f32x2 %0, %1, %2, %3;" : "=l"(d) : "l"(a), "l"(b), "l"(c)); return d;
}
__device__ __forceinline__ u64 fmul2(u64 a, u64 b) {
    u64 d; asm("mul.rn.f32x2 %0, %1, %2;" : "=l"(d) : "l"(a), "l"(b)); return d;
}

__device__ __forceinline__ float2 cmulc(float2 a, float2 b) {
    return make_float2(a.x * b.x - a.y * b.y, a.x * b.y + a.y * b.x);
}

// U = RZ(g)*RY(b)*RX(a); packed coeffs: for element E: (E.x,E.x), (-E.y,E.y).
__device__ void compute_U(const float* p, u64* C) {
    float sx, cx, sy, cy, sz, cz;
    sincosf(0.5f * p[0], &sx, &cx);
    sincosf(0.5f * p[1], &sy, &cy);
    sincosf(0.5f * p[2], &sz, &cz);
    float2 m00 = make_float2( cy * cx,  sy * sx);
    float2 m01 = make_float2(-sy * cx, -cy * sx);
    float2 m10 = make_float2( sy * cx, -cy * sx);
    float2 m11 = make_float2( cy * cx, -sy * sx);
    float2 ezm = make_float2(cz, -sz), ezp = make_float2(cz, sz);
    float2 U0 = cmulc(ezm, m00), U1 = cmulc(ezm, m01);
    float2 U2 = cmulc(ezp, m10), U3 = cmulc(ezp, m11);
    C[0] = pack2(U0.x, U0.x); C[1] = pack2(-U0.y, U0.y);
    C[2] = pack2(U1.x, U1.x); C[3] = pack2(-U1.y, U1.y);
    C[4] = pack2(U2.x, U2.x); C[5] = pack2(-U2.y, U2.y);
    C[6] = pack2(U3.x, U3.x); C[7] = pack2(-U3.y, U3.y);
}

// Gate on register bit J: pairs (r, r^(1<<J)) within the 16-amp register file.
template<int J>
__device__ __forceinline__ void reg_gate(u64* a, const u64* C) {
    u64 c0 = C[0], c1 = C[1], c2 = C[2], c3 = C[3];
    u64 c4 = C[4], c5 = C[5], c6 = C[6], c7 = C[7];
#pragma unroll
    for (int r = 0; r < 16; ++r) {
        if (!(r & (1 << J))) {
            u64 x0 = a[r], x1 = a[r ^ (1 << J)];
            u64 s0 = dswap(x0), s1 = dswap(x1);
            a[r]            = ffma2(c0, x0, ffma2(c1, s0, ffma2(c2, x1, fmul2(c3, s1))));
            a[r ^ (1 << J)] = ffma2(c4, x0, ffma2(c5, s0, ffma2(c6, x1, fmul2(c7, s1))));
        }
    }
}

// Gate on lane bit k via shfl_xor.
__device__ __forceinline__ void lane_gate(u64* a, int l, int k, const u64* C) {
    int bit = (l >> k) & 1;
    u64 d0 = bit ? C[6] : C[0];
    u64 d1 = bit ? C[7] : C[1];
    u64 d2 = bit ? C[4] : C[2];
    u64 d3 = bit ? C[5] : C[3];
#pragma unroll
    for (int r = 0; r < 16; ++r) {
        u64 p = __shfl_xor_sync(0xffffffffu, a[r], 1 << k);
        a[r] = ffma2(d0, a[r], ffma2(d1, dswap(a[r]), ffma2(d2, p, fmul2(d3, dswap(p)))));
    }
}

// ---------- pass H: local bits v0,v1 -> g0,g1 ; v2..v11 -> g11..g20 ----------
template<int FIRST, int DO_CNOT>
__global__ void __launch_bounds__(256, 4) pass_h(const float* __restrict__ params,
                                                 const float* __restrict__ state_in,
                                                 int layer) {
    __shared__ u64 s[4096];
    __shared__ u64 sC[NQ][8];
    int tid = threadIdx.x;
    int l = tid & 31, w = tid >> 5;
    int c = blockIdx.x;  // chunk = g2..g10

    if (FIRST && c == 0) {  // fold accumulator zeroing into layer-0 pass
        if (tid < NQ) { g_zd[tid] = 0.f; g_cr[tid] = 0.f; g_ci[tid] = 0.f; }
        if (tid == NQ) g_S = 0.f;
    }
    if (tid < NQ) compute_U(params + layer * 63 + tid * 3, sC[tid]);

    u64 a[16];
#pragma unroll
    for (int r = 0; r < 16; ++r) {
        int v = l | (r << 5) | (w << 9);
        int g = (v & 3) | (c << 2) | ((v >> 2) << 11);
        if (FIRST) a[r] = pack2(state_in[g], 0.0f);
        else       a[r] = g_psi[g];
    }
    __syncthreads();

    lane_gate(a, l, 2, sC[9]);
    lane_gate(a, l, 3, sC[8]);
    lane_gate(a, l, 4, sC[7]);
    reg_gate<0>(a, sC[6]);
    reg_gate<1>(a, sC[5]);
    reg_gate<2>(a, sC[4]);
    reg_gate<3>(a, sC[3]);

#pragma unroll
    for (int r = 0; r < 16; ++r) s[l | (r << 5) | (w << 9)] = a[r];
    __syncthreads();
#pragma unroll
    for (int r = 0; r < 16; ++r) a[r] = s[l | (w << 5) | (r << 8)];

    reg_gate<1>(a, sC[2]);
    reg_gate<2>(a, sC[1]);
    reg_gate<3>(a, sC[0]);

#pragma unroll
    for (int r = 0; r < 16; ++r) {
        int v = l | (w << 5) | (r << 8);
        int wv = v;
        if (DO_CNOT) {
            int x = v;
            x ^= x >> 1; x ^= x >> 2; x ^= x >> 4; x ^= x >> 8;
            wv = (v & ~0x7FC) | (x & 0x7FC);
        }
        int g = (wv & 3) | (c << 2) | ((wv >> 2) << 11);
        g_psi[g] = a[r];
    }
}

// ---------- pass L: local bits v0..v10 -> g0..g10 ; v11 -> g20 ----------
__global__ void __launch_bounds__(256, 4) pass_l(const float* __restrict__ params, int layer) {
    __shared__ u64 s[4096];
    __shared__ u64 sC[NQ][8];
    int tid = threadIdx.x;
    int l = tid & 31, w = tid >> 5;
    int c = blockIdx.x;  // chunk = g11..g19

    if (tid < NQ) compute_U(params + layer * 63 + tid * 3, sC[tid]);

    u64 a[16];
#pragma unroll
    for (int r = 0; r < 16; ++r) {
        int v = l | (r << 5) | (w << 9);
        int g = (v & 0x7FF) | (c << 11) | ((v >> 11) << 20);
        a[r] = g_psi[g];
    }
    __syncthreads();

    lane_gate(a, l, 0, sC[20]);
    lane_gate(a, l, 1, sC[19]);
    lane_gate(a, l, 2, sC[18]);
    lane_gate(a, l, 3, sC[17]);
    lane_gate(a, l, 4, sC[16]);
    reg_gate<0>(a, sC[15]);
    reg_gate<1>(a, sC[14]);
    reg_gate<2>(a, sC[13]);
    reg_gate<3>(a, sC[12]);

#pragma unroll
    for (int r = 0; r < 16; ++r) s[l | (r << 5) | (w << 9)] = a[r];
    __syncthreads();
#pragma unroll
    for (int r = 0; r < 16; ++r) a[r] = s[l | (w << 5) | (r << 8)];

    reg_gate<1>(a, sC[11]);
    reg_gate<2>(a, sC[10]);

    int K = (c & 1) ? 0x7FF : 0;
#pragma unroll
    for (int r = 0; r < 16; ++r) {
        int v = l | (w << 5) | (r << 8);
        int u = v & 0x7FF;
        int x = u;
        x ^= x >> 1; x ^= x >> 2; x ^= x >> 4; x ^= x >> 8;
        int low = x ^ K;
        int wv = low | ((((v >> 11) ^ low) & 1) << 11);
        int g = (wv & 0x7FF) | (c << 11) | ((wv >> 11) << 20);
        g_psi[g] = a[r];
    }
}

// ---------- measurement reductions ----------
// After layer 2 (state in g_psi), layer 3 = 21 commuting 1-qubit rotations then
// Z measurement. Z'_q = M00*(d0-d1) + 2 Re(c_q * M10) with M = U_q^dag Z U_q,
// c_q = sum psi(bit=0) conj(psi(bit=1)). Only (zd, c) reductions needed here.

__device__ __forceinline__ void wred(float v, float* dst) {
#pragma unroll
    for (int o = 16; o; o >>= 1) v += __shfl_down_sync(0xffffffffu, v, o);
    if ((threadIdx.x & 31) == 0) atomicAdd(dst, v);
}

__device__ __forceinline__ void lane_c(const float2* A, int l, int k, float sk,
                                       float* red_re, float* red_im) {
    float cre = 0.f, cim = 0.f;
#pragma unroll
    for (int r = 0; r < 16; ++r) {
        float pr = __shfl_xor_sync(0xffffffffu, A[r].x, 1 << k);
        float pi = __shfl_xor_sync(0xffffffffu, A[r].y, 1 << k);
        float tre = fmaf(A[r].x, pr, A[r].y * pi);
        float tim = fmaf(A[r].y, pr, -A[r].x * pi);
        cre += tre;
        cim = fmaf(sk, tim, cim);
    }
    wred(0.5f * cre, red_re);
    wred(0.5f * cim, red_im);
}

template<int J>
__device__ __forceinline__ void reg_c(const float2* A, float* red_re, float* red_im) {
    float cre = 0.f, cim = 0.f;
#pragma unroll
    for (int r = 0; r < 16; ++r) {
        if (!(r & (1 << J))) {
            float2 x0 = A[r], x1 = A[r ^ (1 << J)];
            cre = fmaf(x0.x, x1.x, fmaf(x0.y, x1.y, cre));
            cim = fmaf(x0.y, x1.x, fmaf(-x0.x, x1.y, cim));
        }
    }
    wred(cre, red_re);
    wred(cim, red_im);
}

// meas_hl: merged H-tiling (blocks 0..511) + L-tiling (512..1023).
// occ 5 -> 740 CTA slots -> 1.38 waves instead of 1.73.
__global__ void __launch_bounds__(256, 5) meas_hl() {
    __shared__ float2 s[4096];
    __shared__ float red[33];
    int tid = threadIdx.x;
    int l = tid & 31, w = tid >> 5;
    const float2* ps = (const float2*)g_psi;

    if (tid < 33) red[tid] = 0.f;
    __syncthreads();

    if (blockIdx.x < 512) {
        // H tiling: wires 0..9 (bits g11..g20) + S
        int c = blockIdx.x;
        float2 A[16];
#pragma unroll
        for (int r = 0; r < 16; ++r) {
            int v = l | (r << 5) | (w << 9);
            int g = (v & 3) | (c << 2) | ((v >> 2) << 11);
            A[r] = ps[g];
        }

        float S = 0.f, z5 = 0.f, z6 = 0.f, z7 = 0.f, z8 = 0.f;
#pragma unroll
        for (int r = 0; r < 16; ++r) {
            float m = fmaf(A[r].x, A[r].x, A[r].y * A[r].y);
            S += m;
            z5 += (r & 1) ? -m : m;
            z6 += (r & 2) ? -m : m;
            z7 += (r & 4) ? -m : m;
            z8 += (r & 8) ? -m : m;
        }
        float s2 = (l & 4)  ? -1.f : 1.f;
        float s3 = (l & 8)  ? -1.f : 1.f;
        float s4 = (l & 16) ? -1.f : 1.f;
        wred(s2 * S, &red[9]);   // v2 -> wire 9
        wred(s3 * S, &red[8]);
        wred(s4 * S, &red[7]);
        wred(z5, &red[6]);
        wred(z6, &red[5]);
        wred(z7, &red[4]);
        wred(z8, &red[3]);
        wred(((w & 1) ? -S : S), &red[2]);  // v9 -> wire 2
        wred(((w & 2) ? -S : S), &red[1]);
        wred(((w & 4) ? -S : S), &red[0]);
        wred(S, &red[10]);

        lane_c(A, l, 2, s2, &red[11 + 9], &red[21 + 9]);
        lane_c(A, l, 3, s3, &red[11 + 8], &red[21 + 8]);
        lane_c(A, l, 4, s4, &red[11 + 7], &red[21 + 7]);
        reg_c<0>(A, &red[11 + 6], &red[21 + 6]);
        reg_c<1>(A, &red[11 + 5], &red[21 + 5]);
        reg_c<2>(A, &red[11 + 4], &red[21 + 4]);

#pragma unroll
        for (int r = 0; r < 16; ++r) s[l | (r << 5) | (w << 9)] = A[r];
        __syncthreads();
#pragma unroll
        for (int r = 0; r < 16; ++r) A[r] = s[l | (w << 5) | (r << 8)];

        reg_c<0>(A, &red[11 + 3], &red[21 + 3]);
        reg_c<1>(A, &red[11 + 2], &red[21 + 2]);
        reg_c<2>(A, &red[11 + 1], &red[21 + 1]);
        reg_c<3>(A, &red[11 + 0], &red[21 + 0]);

        __syncthreads();
        if (tid < 10) {
            atomicAdd(&g_zd[tid], red[tid]);
            atomicAdd(&g_cr[tid], red[11 + tid]);
            atomicAdd(&g_ci[tid], red[21 + tid]);
        }
        if (tid == 10) atomicAdd(&g_S, red[10]);
    } else {
        // L tiling: wires 10..20 (bits g0..g10)
        int c = blockIdx.x - 512;
        float2 A[16];
#pragma unroll
        for (int r = 0; r < 16; ++r) {
            int v = l | (r << 5) | (w << 9);
            int g = (v & 0x7FF) | (c << 11) | ((v >> 11) << 20);
            A[r] = ps[g];
        }

        float S = 0.f, z5 = 0.f, z6 = 0.f, z7 = 0.f, z8 = 0.f;
#pragma unroll
        for (int r = 0; r < 16; ++r) {
            float m = fmaf(A[r].x, A[r].x, A[r].y * A[r].y);
            S += m;
            z5 += (r & 1) ? -m : m;
            z6 += (r & 2) ? -m : m;
            z7 += (r & 4) ? -m : m;
            z8 += (r & 8) ? -m : m;
        }
        float s0 = (l & 1)  ? -1.f : 1.f;
        float s1 = (l & 2)  ? -1.f : 1.f;
        float s2 = (l & 4)  ? -1.f : 1.f;
        float s3 = (l & 8)  ? -1.f : 1.f;
        float s4 = (l & 16) ? -1.f : 1.f;
        wred(s0 * S, &red[10]);   // wire 20
        wred(s1 * S, &red[9]);
        wred(s2 * S, &red[8]);
        wred(s3 * S, &red[7]);
        wred(s4 * S, &red[6]);
        wred(z5, &red[5]);
        wred(z6, &red[4]);
        wred(z7, &red[3]);
        wred(z8, &red[2]);
        wred(((w & 1) ? -S : S), &red[1]);   // wire 11
        wred(((w & 2) ? -S : S), &red[0]);   // wire 10

        lane_c(A, l, 0, s0, &red[11 + 10], &red[22 + 10]);
        lane_c(A, l, 1, s1, &red[11 + 9],  &red[22 + 9]);
        lane_c(A, l, 2, s2, &red[11 + 8],  &red[22 + 8]);
        lane_c(A, l, 3, s3, &red[11 + 7],  &red[22 + 7]);
        lane_c(A, l, 4, s4, &red[11 + 6],  &red[22 + 6]);
        reg_c<0>(A, &red[11 + 5], &red[22 + 5]);
        reg_c<1>(A, &red[11 + 4], &red[22 + 4]);
        reg_c<2>(A, &red[11 + 3], &red[22 + 3]);

#pragma unroll
        for (int r = 0; r < 16; ++r) s[l | (r << 5) | (w << 9)] = A[r];
        __syncthreads();
#pragma unroll
        for (int r = 0; r < 16; ++r) A[r] = s[l | (w << 5) | (r << 8)];

        reg_c<0>(A, &red[11 + 2], &red[22 + 2]);
        reg_c<1>(A, &red[11 + 1], &red[22 + 1]);
        reg_c<2>(A, &red[11 + 0], &red[22 + 0]);

        __syncthreads();
        if (tid < 11) {
            atomicAdd(&g_zd[10 + tid], red[tid]);
            atomicAdd(&g_cr[10 + tid], red[11 + tid]);
            atomicAdd(&g_ci[10 + tid], red[22 + tid]);
        }
    }
}

// ---------- head ----------
__global__ void head_kernel(const float* __restrict__ params,
                            const float* __restrict__ w, const float* __restrict__ b,
                            float* __restrict__ out) {
    __shared__ float smeas[NQ];
    __shared__ float slog[AD];
    int t = threadIdx.x;
    float S = g_S;
    float inv = (S > 0.0f) ? (1.0f / S) : 0.0f;
    if (t < NQ) {
        const float* p = params + 3 * 63 + t * 3;
        float sx, cx, sy, cy, sz, cz;
        sincosf(0.5f * p[0], &sx, &cx);
        sincosf(0.5f * p[1], &sy, &cy);
        sincosf(0.5f * p[2], &sz, &cz);
        float2 m00 = make_float2( cy * cx,  sy * sx);
        float2 m01 = make_float2(-sy * cx, -cy * sx);
        float2 m10 = make_float2( sy * cx, -cy * sx);
        float2 m11 = make_float2( cy * cx, -sy * sx);
        float2 ezm = make_float2(cz, -sz), ezp = make_float2(cz, sz);
        float2 a = cmulc(ezm, m00);   // u00
        float2 bb = cmulc(ezm, m01);  // u01
        float2 cc = cmulc(ezp, m10);  // u10
        float2 d = cmulc(ezp, m11);   // u11
        float M00 = (a.x * a.x + a.y * a.y) - (cc.x * cc.x + cc.y * cc.y);
        float M10r = (bb.x * a.x + bb.y * a.y) - (d.x * cc.x + d.y * cc.y);
        float M10i = (bb.x * a.y - bb.y * a.x) - (d.x * cc.y - d.y * cc.x);
        smeas[t] = (M00 * g_zd[t] + 2.0f * (M10r * g_cr[t] - M10i * g_ci[t])) * inv;
    }
    __syncthreads();
    if (t < AD) {
        float acc = b[t];
#pragma unroll
        for (int q = 0; q < NQ; ++q) acc = fmaf(w[t * NQ + q], smeas[q], acc);
        slog[t] = acc;
    }
    __syncthreads();
    if (t == 0) {
        float mx = -1e30f;
        for (int ai = 0; ai < AD; ++ai) if (slog[ai] > mx) mx = slog[ai];
        float sum = 0.0f;
        float e[AD];
        for (int ai = 0; ai < AD; ++ai) { e[ai] = expf(slog[ai] - mx); sum += e[ai]; }
        float is = 1.0f / sum;
        for (int ai = 0; ai < AD; ++ai) out[ai] = e[ai] * is;
    }
}

// ---------- launch ----------
extern "C" void kernel_launch(void* const* d_in, const int* in_sizes, int n_in,
                              void* d_out, int out_size) {
    const float* state  = (const float*)d_in[0];  // 2^21 float32
    const float* params = (const float*)d_in[1];  // 252 float32
    const float* hw     = (const float*)d_in[2];  // 18*21 float32
    const float* hb     = (const float*)d_in[3];  // 18 float32
    float* out = (float*)d_out;

    pass_h<1, 1><<<512, 256>>>(params, state, 0);
    pass_l<<<512, 256>>>(params, 0);
    pass_h<0, 1><<<512, 256>>>(params, state, 1);
    pass_l<<<512, 256>>>(params, 1);
    pass_h<0, 1><<<512, 256>>>(params, state, 2);
    pass_l<<<512, 256>>>(params, 2);
    meas_hl<<<1024, 256>>>();
    head_kernel<<<1, 32>>>(params, hw, hb, out);
}